// round 4
// baseline (speedup 1.0000x reference)
#include <cuda_runtime.h>
#include <math.h>

#define TT  50
#define BB  1024
#define BEL 200
#define ST  30
#define ACT 8
#define EMB 1024

// ---- output layout ----
static const size_t OFF_B  = 0;
static const size_t OFF_PS = (size_t)TT * BB * BEL;
static const size_t SZ30   = (size_t)TT * BB * ST;
static const size_t OFF_MP = OFF_PS + SZ30;
static const size_t OFF_SP = OFF_MP + SZ30;
static const size_t OFF_PO = OFF_SP + SZ30;
static const size_t OFF_MQ = OFF_PO + SZ30;
static const size_t OFF_SQ = OFF_MQ + SZ30;

// ---- device scratch ----
__device__ __align__(16) float g_obs[(size_t)TT * BB * BEL];   // obs@Wbq_e^T + b_bq
__device__ __align__(16) float g_act[(size_t)TT * BB * BEL];   // a@Wsa_a^T + b_sa
// packed weights
__device__ __align__(16) float g_Wg2[50 * 600 * 8];   // [k4][tc(600)][2cols][4k]; tc<300: gi, else gh
__device__ __align__(16) float g_Wsa[8 * 200 * 4];    // [k4][j][4k]  (state part only, k padded 30->32)
__device__ __align__(16) float g_Wh2[50 * 200 * 8];   // [k4][p(200)][2cols][4k]; p<100: Wbp, else Wbq_b
__device__ __align__(16) float g_Wo4[50 * 120 * 4];   // [k4][g(120)][4k]; g<60: Wsp else Wsq

typedef unsigned long long u64;

__device__ __forceinline__ void ffma2(u64& acc, u64 a, u64 b) {
    asm("fma.rn.f32x2 %0, %1, %2, %0;" : "+l"(acc) : "l"(a), "l"(b));
}
__device__ __forceinline__ float hsum2(u64 v) {
    float lo, hi;
    asm("mov.b64 {%0,%1}, %2;" : "=f"(lo), "=f"(hi) : "l"(v));
    return lo + hi;
}
__device__ __forceinline__ float sigm(float x) { return 1.f / (1.f + __expf(-x)); }
__device__ __forceinline__ float tanhfast(float x) { return 1.f - 2.f / (__expf(2.f * x) + 1.f); }
__device__ __forceinline__ float softplusf(float x) {
    return fmaxf(x, 0.f) + log1pf(__expf(-fabsf(x)));
}

// ---------------------------------------------------------------------------
// Prep: packed weight layouts.
// ---------------------------------------------------------------------------
#define PREP_N (240000 + 6400 + 80000 + 24000)
__global__ void k_prep(const float* __restrict__ W_sa, const float* __restrict__ W_ih,
                       const float* __restrict__ W_hh, const float* __restrict__ W_bp,
                       const float* __restrict__ W_sp, const float* __restrict__ W_bq,
                       const float* __restrict__ W_sq) {
    int idx = blockIdx.x * blockDim.x + threadIdx.x;
    if (idx < 240000) {  // g_Wg2
        int kk = idx & 3, t1 = idx >> 2;
        int cc = t1 & 1, t2 = t1 >> 1;
        int tc = t2 % 600, k4 = t2 / 600, k = 4 * k4 + kk;
        g_Wg2[idx] = (tc < 300) ? W_ih[(2 * tc + cc) * 200 + k]
                                : W_hh[(2 * (tc - 300) + cc) * 200 + k];
        return;
    }
    idx -= 240000;
    if (idx < 6400) {  // g_Wsa
        int kk = idx & 3, t = idx >> 2;
        int j = t % 200, k4 = t / 200, k = 4 * k4 + kk;
        g_Wsa[idx] = (k < 30) ? W_sa[j * 38 + k] : 0.f;
        return;
    }
    idx -= 6400;
    if (idx < 80000) {  // g_Wh2
        int kk = idx & 3, t1 = idx >> 2;
        int cc = t1 & 1, t2 = t1 >> 1;
        int p = t2 % 200, k4 = t2 / 200, k = 4 * k4 + kk;
        g_Wh2[idx] = (p < 100) ? W_bp[(2 * p + cc) * 200 + k]
                               : W_bq[(size_t)(2 * (p - 100) + cc) * 1224 + k];
        return;
    }
    idx -= 80000;
    if (idx < 24000) {  // g_Wo4
        int kk = idx & 3, t = idx >> 2;
        int g = t % 120, k4 = t / 120, k = 4 * k4 + kk;
        g_Wo4[idx] = (g < 60) ? W_sp[g * 200 + k] : W_sq[(g - 60) * 200 + k];
    }
}

// ---------------------------------------------------------------------------
// Action projection: g_act[t,row,j] = b_sa[j] + sum_i a[t,row,i]*W_sa[j][30+i]
// ---------------------------------------------------------------------------
__global__ void k_act(const float* __restrict__ actions,
                      const float* __restrict__ W_sa, const float* __restrict__ b_sa) {
    size_t idx = (size_t)blockIdx.x * 256 + threadIdx.x;  // < 10,240,000
    int j = (int)(idx % 200);
    size_t row = idx / 200;
    float acc = b_sa[j];
#pragma unroll
    for (int i = 0; i < 8; i++)
        acc = fmaf(actions[row * 8 + i], W_sa[j * 38 + 30 + i], acc);
    g_act[idx] = acc;
}

// ---------------------------------------------------------------------------
// Obs GEMM: g_obs = obs @ Wbq_e^T + b_bq.  M=51200, N=200, K=1024.
// BM=64, BN=200, BK=16. 320 threads = 16 rowg(4 rows) x 20 colg(10 cols).
// f32x2 accumulation, double-buffered smem.
// ---------------------------------------------------------------------------
__global__ __launch_bounds__(320, 1) void k_obs_gemm(const float* __restrict__ A,
                                                     const float* __restrict__ W_bq,
                                                     const float* __restrict__ b_bq) {
    __shared__ __align__(16) float As[2][64 * 20];
    __shared__ __align__(16) float Bs[2][200 * 18];
    const int tid = threadIdx.x;
    const size_t row0 = (size_t)blockIdx.x * 64;
    const int r0 = (tid / 20) * 4;
    const int c0 = (tid % 20) * 10;

    u64 acc[4][10];
#pragma unroll
    for (int i = 0; i < 4; i++)
#pragma unroll
        for (int j = 0; j < 10; j++) acc[i][j] = 0ULL;

    const int arow = tid >> 2, ak4 = tid & 3;   // tid<256 loads A

    // prologue: stage kt=0
    if (tid < 256) {
        float4 v = *(const float4*)&A[(row0 + arow) * EMB + ak4 * 4];
        *(float4*)&As[0][arow * 20 + ak4 * 4] = v;
    }
    for (int idx = tid; idx < 800; idx += 320) {
        int col = idx >> 2, e4 = idx & 3;
        float4 v = *(const float4*)&W_bq[(size_t)col * 1224 + 200 + e4 * 4];
        Bs[0][col * 18 + e4 * 4 + 0] = v.x;
        Bs[0][col * 18 + e4 * 4 + 1] = v.y;
        Bs[0][col * 18 + e4 * 4 + 2] = v.z;
        Bs[0][col * 18 + e4 * 4 + 3] = v.w;
    }
    __syncthreads();

    for (int kti = 0; kti < 64; kti++) {
        const int cur = kti & 1;
        const bool hn = (kti + 1) < 64;
        float4 pa;
        float4 pb[3];
        int nb = 0;
        if (hn) {
            int kt = (kti + 1) * 16;
            if (tid < 256)
                pa = *(const float4*)&A[(row0 + arow) * EMB + kt + ak4 * 4];
            for (int idx = tid; idx < 800; idx += 320) {
                int col = idx >> 2, e4 = idx & 3;
                pb[nb++] = *(const float4*)&W_bq[(size_t)col * 1224 + 200 + kt + e4 * 4];
            }
        }
#pragma unroll
        for (int kp = 0; kp < 8; kp++) {
            u64 a2[4], b2[10];
#pragma unroll
            for (int i = 0; i < 4; i++)
                a2[i] = *(const u64*)&As[cur][(r0 + i) * 20 + 2 * kp];
#pragma unroll
            for (int j = 0; j < 10; j++)
                b2[j] = *(const u64*)&Bs[cur][(c0 + j) * 18 + 2 * kp];
#pragma unroll
            for (int i = 0; i < 4; i++)
#pragma unroll
                for (int j = 0; j < 10; j++) ffma2(acc[i][j], a2[i], b2[j]);
        }
        if (hn) {
            int nxt = cur ^ 1;
            if (tid < 256)
                *(float4*)&As[nxt][arow * 20 + ak4 * 4] = pa;
            nb = 0;
            for (int idx = tid; idx < 800; idx += 320) {
                int col = idx >> 2, e4 = idx & 3;
                float4 v = pb[nb++];
                Bs[nxt][col * 18 + e4 * 4 + 0] = v.x;
                Bs[nxt][col * 18 + e4 * 4 + 1] = v.y;
                Bs[nxt][col * 18 + e4 * 4 + 2] = v.z;
                Bs[nxt][col * 18 + e4 * 4 + 3] = v.w;
            }
        }
        __syncthreads();
    }
#pragma unroll
    for (int i = 0; i < 4; i++)
#pragma unroll
        for (int j = 0; j < 10; j++)
            g_obs[(row0 + r0 + i) * BEL + c0 + j] = hsum2(acc[i][j]) + b_bq[c0 + j];
}

// ---------------------------------------------------------------------------
// Persistent scan kernel: 128 blocks x 640 threads, block owns 8 rows x 50 steps.
// ---------------------------------------------------------------------------
__global__ __launch_bounds__(640, 1) void k_scan(
    const float* __restrict__ nonterm,
    const float* __restrict__ prev_state, const float* __restrict__ prev_belief,
    const float* __restrict__ noise_p, const float* __restrict__ noise_q,
    const float* __restrict__ b_ih, const float* __restrict__ b_hh,
    const float* __restrict__ b_bp, const float* __restrict__ b_sp,
    const float* __restrict__ b_sq, float* __restrict__ out) {
    extern __shared__ float sm[];
    float* s_sh = sm;              // 8*32  = 256
    float* hid  = sm + 256;        // 1600
    float* bel  = sm + 1856;       // 1600
    float* gig  = sm + 3456;       // 9600  (gi @0, gh @4800; aliased: partd / part)
    float* obs  = sm + 13056;      // 1600
    float* hp   = sm + 14656;      // 1600
    float* hq   = sm + 16256;      // 1600
    float* bias = sm + 17856;      // 120
    // total 17976 floats = 71904 B

    const int tid = threadIdx.x;
    const int b0 = blockIdx.x * 8;

    // per-role register biases
    float r_bir = 0.f, r_biz = 0.f, r_bin = 0.f, r_bhr = 0.f, r_bhz = 0.f, r_bhn = 0.f;
    float r_bbp = 0.f;
    if (tid < 200) {
        r_bir = b_ih[tid]; r_biz = b_ih[200 + tid]; r_bin = b_ih[400 + tid];
        r_bhr = b_hh[tid]; r_bhz = b_hh[200 + tid]; r_bhn = b_hh[400 + tid];
        r_bbp = b_bp[tid];
    }
    if (tid < 120) bias[tid] = (tid < 60) ? b_sp[tid] : b_sq[tid - 60];

    // init carries
    for (int idx = tid; idx < 8 * BEL; idx += 640) {
        int bb = idx / BEL, j = idx - bb * BEL;
        bel[idx] = prev_belief[(size_t)(b0 + bb) * BEL + j];
    }
    if (tid < 256) {
        int bb = tid >> 5, c = tid & 31;
        float v = 0.f;
        if (c < 30)
            v = prev_state[(size_t)(b0 + bb) * ST + c] * nonterm[b0 + bb];
        s_sh[tid] = v;
    }
    __syncthreads();

    for (int t = 0; t < TT; t++) {
        // ===== PhA: hidden (tid<200) + obs staging (200<=tid<600) =====
        if (tid < 200) {
            const int j = tid;
            float actp[8];
#pragma unroll
            for (int bb = 0; bb < 8; bb++)
                actp[bb] = g_act[((size_t)t * BB + b0 + bb) * BEL + j];
            u64 acc[8];
#pragma unroll
            for (int bb = 0; bb < 8; bb++) acc[bb] = 0ULL;
#pragma unroll
            for (int k4 = 0; k4 < 8; k4++) {
                ulonglong2 w = *(const ulonglong2*)&g_Wsa[(k4 * 200 + j) * 4];
#pragma unroll
                for (int bb = 0; bb < 8; bb++) {
                    ulonglong2 s = *(const ulonglong2*)&s_sh[bb * 32 + k4 * 4];
                    ffma2(acc[bb], s.x, w.x);
                    ffma2(acc[bb], s.y, w.y);
                }
            }
#pragma unroll
            for (int bb = 0; bb < 8; bb++)
                hid[bb * 200 + j] = fmaxf(hsum2(acc[bb]) + actp[bb], 0.f);
        } else if (tid < 600) {
            int idx = tid - 200;
            float4 v = *(const float4*)&g_obs[((size_t)t * BB + b0) * BEL + idx * 4];
            *(float4*)&obs[idx * 4] = v;
        }
        __syncthreads();

        // ===== PhB: gi + gh, 600 threads, 2 cols each, depth-2 prefetch =====
        if (tid < 600) {
            const float* src = (tid < 300) ? hid : bel;
            const ulonglong2* __restrict__ wp = (const ulonglong2*)g_Wg2 + tid * 2;
            u64 accA[8], accB[8];
#pragma unroll
            for (int bb = 0; bb < 8; bb++) { accA[bb] = 0ULL; accB[bb] = 0ULL; }
            ulonglong2 w0a = wp[0],    w0b = wp[1];
            ulonglong2 w1a = wp[1200], w1b = wp[1201];
#pragma unroll 2
            for (int k4 = 0; k4 < 50; k4++) {
                ulonglong2 wa = w0a, wb = w0b;
                w0a = w1a; w0b = w1b;
                if (k4 + 2 < 50) {
                    w1a = wp[(k4 + 2) * 1200];
                    w1b = wp[(k4 + 2) * 1200 + 1];
                }
#pragma unroll
                for (int bb = 0; bb < 8; bb++) {
                    ulonglong2 h = *(const ulonglong2*)&src[bb * 200 + k4 * 4];
                    ffma2(accA[bb], h.x, wa.x); ffma2(accA[bb], h.y, wa.y);
                    ffma2(accB[bb], h.x, wb.x); ffma2(accB[bb], h.y, wb.y);
                }
            }
            int p = (tid < 300) ? tid : tid - 300;
            float* dst = (tid < 300) ? gig : (gig + 4800);
#pragma unroll
            for (int bb = 0; bb < 8; bb++) {
                dst[bb * 600 + 2 * p]     = hsum2(accA[bb]);
                dst[bb * 600 + 2 * p + 1] = hsum2(accB[bb]);
            }
        }
        __syncthreads();

        // ===== PhC: GRU combine -> new belief =====
        if (tid < 200) {
            const int j = tid;
            const float* gh = gig + 4800;
#pragma unroll
            for (int bb = 0; bb < 8; bb++) {
                float gir = gig[bb * 600 + j], giz = gig[bb * 600 + 200 + j],
                      gin = gig[bb * 600 + 400 + j];
                float ghr = gh[bb * 600 + j], ghz = gh[bb * 600 + 200 + j],
                      ghn = gh[bb * 600 + 400 + j];
                float r = sigm(gir + r_bir + ghr + r_bhr);
                float z = sigm(giz + r_biz + ghz + r_bhz);
                float n = tanhfast(gin + r_bin + r * (ghn + r_bhn));
                float bv = bel[bb * 200 + j];
                float nb = (1.f - z) * n + z * bv;
                bel[bb * 200 + j] = nb;
                out[OFF_B + ((size_t)t * BB + b0 + bb) * BEL + j] = nb;
            }
        }
        __syncthreads();

        // ===== PhD: hp/hq partials, 400 threads = 200 col-pairs x 2 k-halves =====
        if (tid < 400) {
            const int p = tid % 200;     // col-pair: p<100 -> hp, else hq
            const int half = tid / 200;  // k4 range [half*25, half*25+25)
            const ulonglong2* __restrict__ wp = (const ulonglong2*)g_Wh2 + p * 2;
            u64 accA[8], accB[8];
#pragma unroll
            for (int bb = 0; bb < 8; bb++) { accA[bb] = 0ULL; accB[bb] = 0ULL; }
            const int kb = half * 25;
            ulonglong2 w0a = wp[(kb) * 400],     w0b = wp[(kb) * 400 + 1];
            ulonglong2 w1a = wp[(kb + 1) * 400], w1b = wp[(kb + 1) * 400 + 1];
#pragma unroll 2
            for (int kk = 0; kk < 25; kk++) {
                int k4 = kb + kk;
                ulonglong2 wa = w0a, wb = w0b;
                w0a = w1a; w0b = w1b;
                if (kk + 2 < 25) {
                    w1a = wp[(k4 + 2) * 400];
                    w1b = wp[(k4 + 2) * 400 + 1];
                }
#pragma unroll
                for (int bb = 0; bb < 8; bb++) {
                    ulonglong2 h = *(const ulonglong2*)&bel[bb * 200 + k4 * 4];
                    ffma2(accA[bb], h.x, wa.x); ffma2(accA[bb], h.y, wa.y);
                    ffma2(accB[bb], h.x, wb.x); ffma2(accB[bb], h.y, wb.y);
                }
            }
            // partd[half*3200 + bb*400 + col]
#pragma unroll
            for (int bb = 0; bb < 8; bb++) {
                gig[half * 3200 + bb * 400 + 2 * p]     = hsum2(accA[bb]);
                gig[half * 3200 + bb * 400 + 2 * p + 1] = hsum2(accB[bb]);
            }
        }
        __syncthreads();

        // ===== reduce partials -> hp/hq with relu =====
        if (tid < 400) {
            const int col = tid;
#pragma unroll
            for (int bb = 0; bb < 8; bb++) {
                float v = gig[bb * 400 + col] + gig[3200 + bb * 400 + col];
                if (col < 200)
                    hp[bb * 200 + col] = fmaxf(v + r_bbp, 0.f);
                else
                    hq[bb * 200 + col - 200] = fmaxf(v + obs[bb * 200 + col - 200], 0.f);
            }
        }
        __syncthreads();

        // ===== PhE: head projections, k-split 5 =====
        if (tid < 600) {
            const int g = tid % 120, q = tid / 120;
            const float* src = (g < 60) ? hp : hq;
            u64 acc[8];
#pragma unroll
            for (int bb = 0; bb < 8; bb++) acc[bb] = 0ULL;
#pragma unroll
            for (int kk = 0; kk < 10; kk++) {
                int k4 = q * 10 + kk;
                ulonglong2 w = *(const ulonglong2*)&g_Wo4[(k4 * 120 + g) * 4];
#pragma unroll
                for (int bb = 0; bb < 8; bb++) {
                    ulonglong2 h = *(const ulonglong2*)&src[bb * 200 + k4 * 4];
                    ffma2(acc[bb], h.x, w.x);
                    ffma2(acc[bb], h.y, w.y);
                }
            }
#pragma unroll
            for (int bb = 0; bb < 8; bb++)
                gig[q * 960 + bb * 120 + g] = hsum2(acc[bb]);
        }
        __syncthreads();

        // ===== PhF: reduce heads, sample, write outputs, build s_sh(t+1) =====
        if (tid < 240) {
            const int bb = tid / 30, i = tid - bb * 30;
            size_t gidx = ((size_t)t * BB + b0 + bb) * ST + i;
            float np = noise_p[gidx], nq = noise_q[gidx];
            float mp = bias[i], spr = bias[30 + i], mq = bias[60 + i], sqr = bias[90 + i];
#pragma unroll
            for (int q = 0; q < 5; q++) {
                mp  += gig[q * 960 + bb * 120 + i];
                spr += gig[q * 960 + bb * 120 + 30 + i];
                mq  += gig[q * 960 + bb * 120 + 60 + i];
                sqr += gig[q * 960 + bb * 120 + 90 + i];
            }
            float spv = softplusf(spr) + 0.1f;
            float sqv = softplusf(sqr) + 0.1f;
            float po  = fmaf(sqv, nq, mq);
            out[OFF_MP + gidx] = mp;
            out[OFF_SP + gidx] = spv;
            out[OFF_PS + gidx] = fmaf(spv, np, mp);
            out[OFF_MQ + gidx] = mq;
            out[OFF_SQ + gidx] = sqv;
            out[OFF_PO + gidx] = po;
            if (t + 1 < TT)
                s_sh[bb * 32 + i] = po * nonterm[(size_t)(t + 1) * BB + b0 + bb];
        }
        __syncthreads();
    }
}

#define SCAN_SMEM (17976 * 4)

// ---------------------------------------------------------------------------
extern "C" void kernel_launch(void* const* d_in, const int* in_sizes, int n_in,
                              void* d_out, int out_size) {
    const float* prev_state   = (const float*)d_in[0];
    const float* actions      = (const float*)d_in[1];
    const float* prev_belief  = (const float*)d_in[2];
    const float* observations = (const float*)d_in[3];
    const float* nonterm      = (const float*)d_in[4];
    const float* noise_p      = (const float*)d_in[5];
    const float* noise_q      = (const float*)d_in[6];
    const float* W_sa = (const float*)d_in[7];  const float* b_sa = (const float*)d_in[8];
    const float* W_ih = (const float*)d_in[9];  const float* b_ih = (const float*)d_in[10];
    const float* W_hh = (const float*)d_in[11]; const float* b_hh = (const float*)d_in[12];
    const float* W_bp = (const float*)d_in[13]; const float* b_bp = (const float*)d_in[14];
    const float* W_sp = (const float*)d_in[15]; const float* b_sp = (const float*)d_in[16];
    const float* W_bq = (const float*)d_in[17]; const float* b_bq = (const float*)d_in[18];
    const float* W_sq = (const float*)d_in[19]; const float* b_sq = (const float*)d_in[20];
    float* out = (float*)d_out;
    (void)in_sizes; (void)n_in; (void)out_size;

    static int smem_set = 0;
    if (!smem_set) {
        cudaFuncSetAttribute(k_scan, cudaFuncAttributeMaxDynamicSharedMemorySize, SCAN_SMEM);
        smem_set = 1;
    }

    k_prep<<<(PREP_N + 255) / 256, 256>>>(W_sa, W_ih, W_hh, W_bp, W_sp, W_bq, W_sq);
    k_act<<<(TT * BB * BEL) / 256, 256>>>(actions, W_sa, b_sa);
    k_obs_gemm<<<(TT * BB) / 64, 320>>>(observations, W_bq, b_bq);
    k_scan<<<BB / 8, 640, SCAN_SMEM>>>(nonterm, prev_state, prev_belief,
                                       noise_p, noise_q, b_ih, b_hh,
                                       b_bp, b_sp, b_sq, out);
}

// round 5
// speedup vs baseline: 1.0359x; 1.0359x over previous
#include <cuda_runtime.h>
#include <math.h>

#define TT  50
#define BB  1024
#define BEL 200
#define ST  30
#define ACT 8
#define EMB 1024

static const size_t OFF_B  = 0;
static const size_t OFF_PS = (size_t)TT * BB * BEL;
static const size_t SZ30   = (size_t)TT * BB * ST;
static const size_t OFF_MP = OFF_PS + SZ30;
static const size_t OFF_SP = OFF_MP + SZ30;
static const size_t OFF_PO = OFF_SP + SZ30;
static const size_t OFF_MQ = OFF_PO + SZ30;
static const size_t OFF_SQ = OFF_MQ + SZ30;

__device__ __align__(16) float g_obs[(size_t)TT * BB * BEL];
__device__ __align__(16) float g_act[(size_t)TT * BB * BEL];
// per-step weight stream, 87 chunks in consumption order (350400 floats):
// [0,6400) Wsa 2x3200 [k4][j(200)][4] ; [6400,246400) Wg 50x4800 [tc(600)][2][4]
// [246400,326400) Wh 25x3200 [half(2)][p(200)][2][4] ; [326400,350400) Wo 10x2400 [q(5)][g(120)][4]
__device__ __align__(16) float g_stream[350400];

typedef unsigned long long u64;

__device__ __forceinline__ void ffma2(u64& acc, u64 a, u64 b) {
    asm("fma.rn.f32x2 %0, %1, %2, %0;" : "+l"(acc) : "l"(a), "l"(b));
}
__device__ __forceinline__ float hsum2(u64 v) {
    float lo, hi;
    asm("mov.b64 {%0,%1}, %2;" : "=f"(lo), "=f"(hi) : "l"(v));
    return lo + hi;
}
__device__ __forceinline__ float sigm(float x) { return 1.f / (1.f + __expf(-x)); }
__device__ __forceinline__ float tanhfast(float x) { return 1.f - 2.f / (__expf(2.f * x) + 1.f); }
__device__ __forceinline__ float softplusf(float x) {
    return fmaxf(x, 0.f) + log1pf(__expf(-fabsf(x)));
}
__device__ __forceinline__ unsigned s2u(const void* p) {
    unsigned r;
    asm("{.reg .u64 t; cvta.to.shared.u64 t, %1; cvt.u32.u64 %0, t;}" : "=r"(r) : "l"(p));
    return r;
}
__device__ __forceinline__ unsigned mb_try(unsigned mbar, unsigned par) {
    unsigned d;
    asm volatile(
        "{.reg .pred p; mbarrier.try_wait.parity.acquire.cta.shared::cta.b64 p, [%1], %2;"
        " selp.b32 %0, 1, 0, p;}" : "=r"(d) : "r"(mbar), "r"(par) : "memory");
    return d;
}
__device__ __forceinline__ void mb_wait(unsigned m, unsigned p) { while (!mb_try(m, p)) {} }
__device__ __forceinline__ void mb_wait2(unsigned m0, unsigned p0, unsigned m1, unsigned p1) {
    unsigned d0 = 0, d1 = 0;
    do { if (!d0) d0 = mb_try(m0, p0); if (!d1) d1 = mb_try(m1, p1); } while (!(d0 & d1));
}
__device__ __forceinline__ void mb_arrive(unsigned m) {
    asm volatile("mbarrier.arrive.shared.b64 _, [%0];" :: "r"(m) : "memory");
}
__device__ __forceinline__ void mb_init(unsigned m, unsigned c) {
    asm volatile("mbarrier.init.shared.b64 [%0], %1;" :: "r"(m), "r"(c) : "memory");
}
__device__ __forceinline__ void mb_tx(unsigned m, unsigned bytes) {
    asm volatile("mbarrier.arrive.expect_tx.shared.b64 _, [%0], %1;"
                 :: "r"(m), "r"(bytes) : "memory");
}
__device__ __forceinline__ void bulk_g2s(unsigned dst, const void* src, unsigned bytes, unsigned m) {
    asm volatile(
        "cp.async.bulk.shared::cta.global.mbarrier::complete_tx::bytes [%0], [%1], %2, [%3];"
        :: "r"(dst), "l"(src), "r"(bytes), "r"(m) : "memory");
}
__device__ __forceinline__ void barc() { asm volatile("bar.sync 1, 608;" ::: "memory"); }

// ---------------------------------------------------------------------------
#define PREP_N 350400
__global__ void k_prep(const float* __restrict__ W_sa, const float* __restrict__ W_ih,
                       const float* __restrict__ W_hh, const float* __restrict__ W_bp,
                       const float* __restrict__ W_sp, const float* __restrict__ W_bq,
                       const float* __restrict__ W_sq) {
    int idx = blockIdx.x * blockDim.x + threadIdx.x;
    if (idx >= PREP_N) return;
    float v;
    if (idx < 6400) {
        int k4 = idx / 800, r = idx % 800, j = r >> 2, k = k4 * 4 + (r & 3);
        v = (k < 30) ? W_sa[j * 38 + k] : 0.f;
    } else if (idx < 246400) {
        int l = idx - 6400, k4 = l / 4800, r = l % 4800;
        int tc = r >> 3, cc = (r >> 2) & 1, k = k4 * 4 + (r & 3);
        v = (tc < 300) ? W_ih[(2 * tc + cc) * 200 + k] : W_hh[(2 * (tc - 300) + cc) * 200 + k];
    } else if (idx < 326400) {
        int l = idx - 246400, ck = l / 3200, r = l % 3200;
        int half = r / 1600, r2 = r % 1600;
        int p = r2 >> 3, cc = (r2 >> 2) & 1, k = (half * 25 + ck) * 4 + (r2 & 3);
        v = (p < 100) ? W_bp[(2 * p + cc) * 200 + k]
                      : W_bq[(size_t)(2 * (p - 100) + cc) * 1224 + k];
    } else {
        int l = idx - 326400, ck = l / 2400, r = l % 2400;
        int q = r / 480, r2 = r % 480, g = r2 >> 2, k = (q * 10 + ck) * 4 + (r2 & 3);
        v = (g < 60) ? W_sp[g * 200 + k] : W_sq[(g - 60) * 200 + k];
    }
    g_stream[idx] = v;
}

__global__ void k_act(const float* __restrict__ actions,
                      const float* __restrict__ W_sa, const float* __restrict__ b_sa) {
    size_t idx = (size_t)blockIdx.x * 256 + threadIdx.x;
    int j = (int)(idx % 200);
    size_t row = idx / 200;
    float acc = b_sa[j];
#pragma unroll
    for (int i = 0; i < 8; i++)
        acc = fmaf(actions[row * 8 + i], W_sa[j * 38 + 30 + i], acc);
    g_act[idx] = acc;
}

// ---------------------------------------------------------------------------
__global__ __launch_bounds__(320, 1) void k_obs_gemm(const float* __restrict__ A,
                                                     const float* __restrict__ W_bq,
                                                     const float* __restrict__ b_bq) {
    __shared__ __align__(16) float As[2][64 * 20];
    __shared__ __align__(16) float Bs[2][200 * 18];
    const int tid = threadIdx.x;
    const size_t row0 = (size_t)blockIdx.x * 64;
    const int r0 = (tid / 20) * 4, c0 = (tid % 20) * 10;
    u64 acc[4][10];
#pragma unroll
    for (int i = 0; i < 4; i++)
#pragma unroll
        for (int j = 0; j < 10; j++) acc[i][j] = 0ULL;
    const int arow = tid >> 2, ak4 = tid & 3;
    if (tid < 256)
        *(float4*)&As[0][arow * 20 + ak4 * 4] = *(const float4*)&A[(row0 + arow) * EMB + ak4 * 4];
    for (int idx = tid; idx < 800; idx += 320) {
        int col = idx >> 2, e4 = idx & 3;
        float4 v = *(const float4*)&W_bq[(size_t)col * 1224 + 200 + e4 * 4];
        Bs[0][col * 18 + e4 * 4 + 0] = v.x; Bs[0][col * 18 + e4 * 4 + 1] = v.y;
        Bs[0][col * 18 + e4 * 4 + 2] = v.z; Bs[0][col * 18 + e4 * 4 + 3] = v.w;
    }
    __syncthreads();
    for (int kti = 0; kti < 64; kti++) {
        const int cur = kti & 1;
        const bool hn = (kti + 1) < 64;
        float4 pa; float4 pb[3]; int nb = 0;
        if (hn) {
            int kt = (kti + 1) * 16;
            if (tid < 256) pa = *(const float4*)&A[(row0 + arow) * EMB + kt + ak4 * 4];
            for (int idx = tid; idx < 800; idx += 320) {
                int col = idx >> 2, e4 = idx & 3;
                pb[nb++] = *(const float4*)&W_bq[(size_t)col * 1224 + 200 + kt + e4 * 4];
            }
        }
#pragma unroll
        for (int kp = 0; kp < 8; kp++) {
            u64 a2[4], b2[10];
#pragma unroll
            for (int i = 0; i < 4; i++) a2[i] = *(const u64*)&As[cur][(r0 + i) * 20 + 2 * kp];
#pragma unroll
            for (int j = 0; j < 10; j++) b2[j] = *(const u64*)&Bs[cur][(c0 + j) * 18 + 2 * kp];
#pragma unroll
            for (int i = 0; i < 4; i++)
#pragma unroll
                for (int j = 0; j < 10; j++) ffma2(acc[i][j], a2[i], b2[j]);
        }
        if (hn) {
            int nxt = cur ^ 1;
            if (tid < 256) *(float4*)&As[nxt][arow * 20 + ak4 * 4] = pa;
            nb = 0;
            for (int idx = tid; idx < 800; idx += 320) {
                int col = idx >> 2, e4 = idx & 3;
                float4 v = pb[nb++];
                Bs[nxt][col * 18 + e4 * 4 + 0] = v.x; Bs[nxt][col * 18 + e4 * 4 + 1] = v.y;
                Bs[nxt][col * 18 + e4 * 4 + 2] = v.z; Bs[nxt][col * 18 + e4 * 4 + 3] = v.w;
            }
        }
        __syncthreads();
    }
#pragma unroll
    for (int i = 0; i < 4; i++)
#pragma unroll
        for (int j = 0; j < 10; j++)
            g_obs[(row0 + r0 + i) * BEL + c0 + j] = hsum2(acc[i][j]) + b_bq[c0 + j];
}

// ---------------------------------------------------------------------------
// Persistent scan: 19 consumer warps + 1 producer warp streaming g_stream
// through a 7-slot x 19.2KB smem ring (cp.async.bulk + mbarrier).
// ---------------------------------------------------------------------------
#define RING_F 33600
#define SLOT_F 4800
#define NSLOT  7
#define MB_OFF (51576 * 4)
#define SCAN_SMEM (MB_OFF + 128)
#define NEXT(s, p) { s = rs; p = rp; if (++rs == NSLOT) { rs = 0; rp ^= 1; } }

__global__ __launch_bounds__(640, 1) void k_scan(
    const float* __restrict__ nonterm,
    const float* __restrict__ prev_state, const float* __restrict__ prev_belief,
    const float* __restrict__ noise_p, const float* __restrict__ noise_q,
    const float* __restrict__ b_ih, const float* __restrict__ b_hh,
    const float* __restrict__ b_bp, const float* __restrict__ b_sp,
    const float* __restrict__ b_sq, float* __restrict__ out) {
    extern __shared__ __align__(16) float sm[];
    float* ring = sm;
    float* s_sh = sm + RING_F;   // 256
    float* hid  = s_sh + 256;    // 1600
    float* bel  = hid + 1600;    // 1600
    float* gig  = bel + 1600;    // 9600
    float* obs  = gig + 9600;    // 1600
    float* hp   = obs + 1600;    // 1600
    float* hq   = hp + 1600;     // 1600
    float* bias = hq + 1600;     // 120
    const unsigned smu = s2u(sm), mbu = smu + MB_OFF;  // full[s]=+16s, empty[s]=+16s+8
    const int tid = threadIdx.x;
    const int b0 = blockIdx.x * 8;

    if (tid == 0)
#pragma unroll
        for (int s = 0; s < NSLOT; s++) { mb_init(mbu + 16 * s, 1); mb_init(mbu + 16 * s + 8, 19); }
    __syncthreads();

    if (tid >= 608) {            // ---- producer warp ----
        if (tid == 608) {
            int rs = 0, rp = 0, l = 0;
            for (int c = 0; c < TT * 87; c++) {
                mb_wait(mbu + 16 * rs + 8, rp ^ 1);
                int off, szb;
                if (l < 2)       { off = l * 3200;               szb = 12800; }
                else if (l < 52) { off = 6400 + (l - 2) * 4800;  szb = 19200; }
                else if (l < 77) { off = 246400 + (l - 52) * 3200; szb = 12800; }
                else             { off = 326400 + (l - 77) * 2400; szb = 9600; }
                unsigned fb = mbu + 16 * rs;
                mb_tx(fb, (unsigned)szb);
                bulk_g2s(smu + (unsigned)rs * (SLOT_F * 4), g_stream + off, (unsigned)szb, fb);
                if (++rs == NSLOT) { rs = 0; rp ^= 1; }
                if (++l == 87) l = 0;
            }
        }
        return;
    }

    // ---- consumers ----
    float r_bir = 0.f, r_biz = 0.f, r_bin = 0.f, r_bhr = 0.f, r_bhz = 0.f, r_bhn = 0.f, r_bbp = 0.f;
    if (tid < 200) {
        r_bir = b_ih[tid]; r_biz = b_ih[200 + tid]; r_bin = b_ih[400 + tid];
        r_bhr = b_hh[tid]; r_bhz = b_hh[200 + tid]; r_bhn = b_hh[400 + tid];
        r_bbp = b_bp[tid];
    }
    if (tid < 120) bias[tid] = (tid < 60) ? b_sp[tid] : b_sq[tid - 60];
    for (int idx = tid; idx < 8 * BEL; idx += 608) {
        int bb = idx / BEL, j = idx - bb * BEL;
        bel[idx] = prev_belief[(size_t)(b0 + bb) * BEL + j];
    }
    if (tid < 256) {
        int bb = tid >> 5, c = tid & 31;
        s_sh[tid] = (c < 30) ? prev_state[(size_t)(b0 + bb) * ST + c] * nonterm[b0 + bb] : 0.f;
    }
    barc();

    int rs = 0, rp = 0;
    const bool lane0 = ((tid & 31) == 0);

    for (int t = 0; t < TT; t++) {
        // ===== PhA: hidden (chunks 0,1) + obs prefetch =====
        {
            float actp[8]; float4 obsv;
            if (tid < 200) {
#pragma unroll
                for (int bb = 0; bb < 8; bb++)
                    actp[bb] = g_act[((size_t)t * BB + b0 + bb) * BEL + tid];
            } else if (tid < 600) {
                obsv = *(const float4*)&g_obs[((size_t)t * BB + b0) * BEL + (tid - 200) * 4];
            }
            int s0, p0, s1, p1; NEXT(s0, p0) NEXT(s1, p1)
            mb_wait2(mbu + 16 * s0, p0, mbu + 16 * s1, p1);
            if (tid < 200) {
                u64 acc[8];
#pragma unroll
                for (int bb = 0; bb < 8; bb++) acc[bb] = 0ULL;
                const float* r0 = &ring[s0 * SLOT_F + tid * 4];
                const float* r1 = &ring[s1 * SLOT_F + tid * 4];
#pragma unroll
                for (int k4 = 0; k4 < 4; k4++) {
                    ulonglong2 w = *(const ulonglong2*)(r0 + k4 * 800);
                    ulonglong2 w2 = *(const ulonglong2*)(r1 + k4 * 800);
#pragma unroll
                    for (int bb = 0; bb < 8; bb++) {
                        ulonglong2 s = *(const ulonglong2*)&s_sh[bb * 32 + k4 * 4];
                        ulonglong2 s2 = *(const ulonglong2*)&s_sh[bb * 32 + (k4 + 4) * 4];
                        ffma2(acc[bb], s.x, w.x);  ffma2(acc[bb], s.y, w.y);
                        ffma2(acc[bb], s2.x, w2.x); ffma2(acc[bb], s2.y, w2.y);
                    }
                }
#pragma unroll
                for (int bb = 0; bb < 8; bb++)
                    hid[bb * 200 + tid] = fmaxf(hsum2(acc[bb]) + actp[bb], 0.f);
            }
            __syncwarp();
            if (lane0) { mb_arrive(mbu + 16 * s0 + 8); mb_arrive(mbu + 16 * s1 + 8); }
            if (tid >= 200 && tid < 600) *(float4*)&obs[(tid - 200) * 4] = obsv;
        }
        barc();

        // ===== PhB: gi + gh (chunks 2..51) =====
        {
            u64 accA[8], accB[8];
#pragma unroll
            for (int bb = 0; bb < 8; bb++) { accA[bb] = 0ULL; accB[bb] = 0ULL; }
            const float* src = (tid < 300) ? hid : bel;
            for (int kp = 0; kp < 25; kp++) {
                int s0, p0, s1, p1; NEXT(s0, p0) NEXT(s1, p1)
                mb_wait2(mbu + 16 * s0, p0, mbu + 16 * s1, p1);
                if (tid < 600) {
                    const float* w0 = &ring[s0 * SLOT_F + tid * 8];
                    const float* w1 = &ring[s1 * SLOT_F + tid * 8];
                    ulonglong2 wa0 = *(const ulonglong2*)w0, wb0 = *(const ulonglong2*)(w0 + 4);
                    ulonglong2 wa1 = *(const ulonglong2*)w1, wb1 = *(const ulonglong2*)(w1 + 4);
                    int k0 = 2 * kp, k1 = 2 * kp + 1;
#pragma unroll
                    for (int bb = 0; bb < 8; bb++) {
                        ulonglong2 h0 = *(const ulonglong2*)&src[bb * 200 + k0 * 4];
                        ulonglong2 h1 = *(const ulonglong2*)&src[bb * 200 + k1 * 4];
                        ffma2(accA[bb], h0.x, wa0.x); ffma2(accA[bb], h0.y, wa0.y);
                        ffma2(accB[bb], h0.x, wb0.x); ffma2(accB[bb], h0.y, wb0.y);
                        ffma2(accA[bb], h1.x, wa1.x); ffma2(accA[bb], h1.y, wa1.y);
                        ffma2(accB[bb], h1.x, wb1.x); ffma2(accB[bb], h1.y, wb1.y);
                    }
                }
                __syncwarp();
                if (lane0) { mb_arrive(mbu + 16 * s0 + 8); mb_arrive(mbu + 16 * s1 + 8); }
            }
            if (tid < 600) {
                int p = (tid < 300) ? tid : tid - 300;
                float* dst = (tid < 300) ? gig : (gig + 4800);
#pragma unroll
                for (int bb = 0; bb < 8; bb++) {
                    dst[bb * 600 + 2 * p]     = hsum2(accA[bb]);
                    dst[bb * 600 + 2 * p + 1] = hsum2(accB[bb]);
                }
            }
        }
        barc();

        // ===== PhC: GRU combine =====
        if (tid < 200) {
            const int j = tid;
            const float* gh = gig + 4800;
#pragma unroll
            for (int bb = 0; bb < 8; bb++) {
                float r = sigm(gig[bb * 600 + j] + r_bir + gh[bb * 600 + j] + r_bhr);
                float z = sigm(gig[bb * 600 + 200 + j] + r_biz + gh[bb * 600 + 200 + j] + r_bhz);
                float n = tanhfast(gig[bb * 600 + 400 + j] + r_bin +
                                   r * (gh[bb * 600 + 400 + j] + r_bhn));
                float nb = (1.f - z) * n + z * bel[bb * 200 + j];
                bel[bb * 200 + j] = nb;
                out[OFF_B + ((size_t)t * BB + b0 + bb) * BEL + j] = nb;
            }
        }
        barc();

        // ===== PhD: hp/hq partials (chunks 52..76) =====
        {
            u64 accA[8], accB[8];
#pragma unroll
            for (int bb = 0; bb < 8; bb++) { accA[bb] = 0ULL; accB[bb] = 0ULL; }
            const int p = tid % 200, half = tid / 200;
            for (int kp = 0; kp < 12; kp++) {
                int s0, p0, s1, p1; NEXT(s0, p0) NEXT(s1, p1)
                mb_wait2(mbu + 16 * s0, p0, mbu + 16 * s1, p1);
                if (tid < 400) {
                    const float* w0 = &ring[s0 * SLOT_F + half * 1600 + p * 8];
                    const float* w1 = &ring[s1 * SLOT_F + half * 1600 + p * 8];
                    ulonglong2 wa0 = *(const ulonglong2*)w0, wb0 = *(const ulonglong2*)(w0 + 4);
                    ulonglong2 wa1 = *(const ulonglong2*)w1, wb1 = *(const ulonglong2*)(w1 + 4);
                    int k0 = half * 25 + 2 * kp, k1 = k0 + 1;
#pragma unroll
                    for (int bb = 0; bb < 8; bb++) {
                        ulonglong2 h0 = *(const ulonglong2*)&bel[bb * 200 + k0 * 4];
                        ulonglong2 h1 = *(const ulonglong2*)&bel[bb * 200 + k1 * 4];
                        ffma2(accA[bb], h0.x, wa0.x); ffma2(accA[bb], h0.y, wa0.y);
                        ffma2(accB[bb], h0.x, wb0.x); ffma2(accB[bb], h0.y, wb0.y);
                        ffma2(accA[bb], h1.x, wa1.x); ffma2(accA[bb], h1.y, wa1.y);
                        ffma2(accB[bb], h1.x, wb1.x); ffma2(accB[bb], h1.y, wb1.y);
                    }
                }
                __syncwarp();
                if (lane0) { mb_arrive(mbu + 16 * s0 + 8); mb_arrive(mbu + 16 * s1 + 8); }
            }
            {   // remainder chunk ck=24
                int s0, p0; NEXT(s0, p0)
                mb_wait(mbu + 16 * s0, p0);
                if (tid < 400) {
                    const float* w0 = &ring[s0 * SLOT_F + half * 1600 + p * 8];
                    ulonglong2 wa0 = *(const ulonglong2*)w0, wb0 = *(const ulonglong2*)(w0 + 4);
                    int k0 = half * 25 + 24;
#pragma unroll
                    for (int bb = 0; bb < 8; bb++) {
                        ulonglong2 h0 = *(const ulonglong2*)&bel[bb * 200 + k0 * 4];
                        ffma2(accA[bb], h0.x, wa0.x); ffma2(accA[bb], h0.y, wa0.y);
                        ffma2(accB[bb], h0.x, wb0.x); ffma2(accB[bb], h0.y, wb0.y);
                    }
                }
                __syncwarp();
                if (lane0) mb_arrive(mbu + 16 * s0 + 8);
            }
            if (tid < 400) {
#pragma unroll
                for (int bb = 0; bb < 8; bb++) {
                    gig[half * 3200 + bb * 400 + 2 * p]     = hsum2(accA[bb]);
                    gig[half * 3200 + bb * 400 + 2 * p + 1] = hsum2(accB[bb]);
                }
            }
        }
        barc();

        // ===== reduce partials -> hp/hq =====
        if (tid < 400) {
#pragma unroll
            for (int bb = 0; bb < 8; bb++) {
                float v = gig[bb * 400 + tid] + gig[3200 + bb * 400 + tid];
                if (tid < 200) hp[bb * 200 + tid] = fmaxf(v + r_bbp, 0.f);
                else hq[bb * 200 + tid - 200] = fmaxf(v + obs[bb * 200 + tid - 200], 0.f);
            }
        }
        barc();

        // ===== PhE: head projections (chunks 77..86) =====
        {
            u64 acc[8];
#pragma unroll
            for (int bb = 0; bb < 8; bb++) acc[bb] = 0ULL;
            const int g = tid % 120, q = tid / 120;
            const float* src = (g < 60) ? hp : hq;
            for (int kp = 0; kp < 5; kp++) {
                int s0, p0, s1, p1; NEXT(s0, p0) NEXT(s1, p1)
                mb_wait2(mbu + 16 * s0, p0, mbu + 16 * s1, p1);
                if (tid < 600) {
                    ulonglong2 w0 = *(const ulonglong2*)&ring[s0 * SLOT_F + q * 480 + g * 4];
                    ulonglong2 w1 = *(const ulonglong2*)&ring[s1 * SLOT_F + q * 480 + g * 4];
                    int k0 = q * 10 + 2 * kp, k1 = k0 + 1;
#pragma unroll
                    for (int bb = 0; bb < 8; bb++) {
                        ulonglong2 h0 = *(const ulonglong2*)&src[bb * 200 + k0 * 4];
                        ulonglong2 h1 = *(const ulonglong2*)&src[bb * 200 + k1 * 4];
                        ffma2(acc[bb], h0.x, w0.x); ffma2(acc[bb], h0.y, w0.y);
                        ffma2(acc[bb], h1.x, w1.x); ffma2(acc[bb], h1.y, w1.y);
                    }
                }
                __syncwarp();
                if (lane0) { mb_arrive(mbu + 16 * s0 + 8); mb_arrive(mbu + 16 * s1 + 8); }
            }
            if (tid < 600) {
#pragma unroll
                for (int bb = 0; bb < 8; bb++)
                    gig[q * 960 + bb * 120 + g] = hsum2(acc[bb]);
            }
        }
        barc();

        // ===== PhF: reduce heads, sample, write outputs, next s_sh =====
        if (tid < 240) {
            const int bb = tid / 30, i = tid - bb * 30;
            size_t gidx = ((size_t)t * BB + b0 + bb) * ST + i;
            float np = noise_p[gidx], nq = noise_q[gidx];
            float mp = bias[i], spr = bias[30 + i], mq = bias[60 + i], sqr = bias[90 + i];
#pragma unroll
            for (int q = 0; q < 5; q++) {
                mp  += gig[q * 960 + bb * 120 + i];
                spr += gig[q * 960 + bb * 120 + 30 + i];
                mq  += gig[q * 960 + bb * 120 + 60 + i];
                sqr += gig[q * 960 + bb * 120 + 90 + i];
            }
            float spv = softplusf(spr) + 0.1f;
            float sqv = softplusf(sqr) + 0.1f;
            float po  = fmaf(sqv, nq, mq);
            out[OFF_MP + gidx] = mp;
            out[OFF_SP + gidx] = spv;
            out[OFF_PS + gidx] = fmaf(spv, np, mp);
            out[OFF_MQ + gidx] = mq;
            out[OFF_SQ + gidx] = sqv;
            out[OFF_PO + gidx] = po;
            if (t + 1 < TT)
                s_sh[bb * 32 + i] = po * nonterm[(size_t)(t + 1) * BB + b0 + bb];
        }
        barc();
    }
}

// ---------------------------------------------------------------------------
extern "C" void kernel_launch(void* const* d_in, const int* in_sizes, int n_in,
                              void* d_out, int out_size) {
    const float* prev_state   = (const float*)d_in[0];
    const float* actions      = (const float*)d_in[1];
    const float* prev_belief  = (const float*)d_in[2];
    const float* observations = (const float*)d_in[3];
    const float* nonterm      = (const float*)d_in[4];
    const float* noise_p      = (const float*)d_in[5];
    const float* noise_q      = (const float*)d_in[6];
    const float* W_sa = (const float*)d_in[7];  const float* b_sa = (const float*)d_in[8];
    const float* W_ih = (const float*)d_in[9];  const float* b_ih = (const float*)d_in[10];
    const float* W_hh = (const float*)d_in[11]; const float* b_hh = (const float*)d_in[12];
    const float* W_bp = (const float*)d_in[13]; const float* b_bp = (const float*)d_in[14];
    const float* W_sp = (const float*)d_in[15]; const float* b_sp = (const float*)d_in[16];
    const float* W_bq = (const float*)d_in[17]; const float* b_bq = (const float*)d_in[18];
    const float* W_sq = (const float*)d_in[19]; const float* b_sq = (const float*)d_in[20];
    float* out = (float*)d_out;
    (void)in_sizes; (void)n_in; (void)out_size;

    static int done = 0;
    if (!done) {
        cudaFuncSetAttribute(k_scan, cudaFuncAttributeMaxDynamicSharedMemorySize, SCAN_SMEM);
        done = 1;
    }
    k_prep<<<(PREP_N + 255) / 256, 256>>>(W_sa, W_ih, W_hh, W_bp, W_sp, W_bq, W_sq);
    k_act<<<(TT * BB * BEL) / 256, 256>>>(actions, W_sa, b_sa);
    k_obs_gemm<<<(TT * BB) / 64, 320>>>(observations, W_bq, b_bq);
    k_scan<<<BB / 8, 640, SCAN_SMEM>>>(nonterm, prev_state, prev_belief, noise_p, noise_q,
                                       b_ih, b_hh, b_bp, b_sp, b_sq, out);
}